// round 5
// baseline (speedup 1.0000x reference)
#include <cuda_runtime.h>
#include <cuda_bf16.h>

#define NT 4096

static __device__ __forceinline__ float tanha(float x) {
    float y; asm("tanh.approx.f32 %0, %1;" : "=f"(y) : "f"(x)); return y;
}
static __device__ __forceinline__ float sigm(float x) {   // exact identity; approx only via TANH
    return fmaf(tanha(0.5f * x), 0.5f, 0.5f);
}
static __device__ __forceinline__ float frcpa(float x) {
    float y; asm("rcp.approx.f32 %0, %1;" : "=f"(y) : "f"(x)); return y;
}

// Per-chain state: full depth-2 signature per lane (no cross-lane reduce — round-4 lesson),
// depth-4 input prefetch ring, fg/x-proj pipelined one step ahead (off the h-chain).
#define DECL_STATE(P) \
    float P##L10=0.f,P##L11=0.f,P##L12=0.f,P##L13=0.f; \
    float P##T0=0.f,P##T1=0.f,P##T2=0.f,P##T3=0.f,P##T4=0.f,P##T5=0.f,P##T6=0.f,P##T7=0.f; \
    float P##T8=0.f,P##T9=0.f,P##T10=0.f,P##T11=0.f,P##T12=0.f,P##T13=0.f,P##T14=0.f,P##T15=0.f; \
    float P##h,P##c,P##p0,P##p1,P##p2,P##tf=0.f; \
    float P##fgv,P##gi,P##gc,P##go,P##fgn,P##ni,P##nc,P##no; \
    float P##x0_0,P##x0_1,P##x0_2,P##x0_3; \
    float P##x1_0,P##x1_1,P##x1_2,P##x1_3; \
    float P##x2_0,P##x2_1,P##x2_2,P##x2_3; \
    const float* P##xp; float* P##op;

// Advance signature to step T_+1 (consumes ring slot S = (T_+1)&3, refills with x_{T_+5});
// produce forget gate + x-projections for step T_+1. Input-only -> fully off the h critical chain.
#define STEP_C(P, T_, S) do { \
    float xn0 = P##x0_##S, xn1 = P##x1_##S, xn2 = P##x2_##S; \
    int tl_ = (T_) + 5; tl_ = tl_ > 4095 ? 4095 : tl_; \
    const float* aa_ = P##xp + tl_ * 3; \
    P##x0_##S = __ldg(aa_); P##x1_##S = __ldg(aa_ + 1); P##x2_##S = __ldg(aa_ + 2); \
    P##tf += 1.f; \
    float d1 = xn0 - P##p0, d2 = xn1 - P##p1, d3 = xn2 - P##p2; \
    P##p0 = xn0; P##p1 = xn1; P##p2 = xn2; \
    float q0 = P##L10 + HDX0; \
    float q1 = fmaf(0.5f, d1, P##L11); \
    float q2 = fmaf(0.5f, d2, P##L12); \
    float q3 = fmaf(0.5f, d3, P##L13); \
    P##T0 = fmaf(q0,DX0,P##T0);  P##T1 = fmaf(q0,d1,P##T1);  P##T2 = fmaf(q0,d2,P##T2);   P##T3 = fmaf(q0,d3,P##T3); \
    P##T4 = fmaf(q1,DX0,P##T4);  P##T5 = fmaf(q1,d1,P##T5);  P##T6 = fmaf(q1,d2,P##T6);   P##T7 = fmaf(q1,d3,P##T7); \
    P##T8 = fmaf(q2,DX0,P##T8);  P##T9 = fmaf(q2,d1,P##T9);  P##T10 = fmaf(q2,d2,P##T10); P##T11 = fmaf(q2,d3,P##T11); \
    P##T12 = fmaf(q3,DX0,P##T12);P##T13 = fmaf(q3,d1,P##T13);P##T14 = fmaf(q3,d2,P##T14); P##T15 = fmaf(q3,d3,P##T15); \
    P##L10 += DX0; P##L11 += d1; P##L12 += d2; P##L13 += d3; \
    float a0 = fmaf(P##L10,F1,F0); a0 = fmaf(P##T0,F5,a0);  a0 = fmaf(P##T4,F9,a0);   a0 = fmaf(P##T8,F13,a0);  a0 = fmaf(P##T12,F17,a0); \
    float a1 = P##L11 * F2;        a1 = fmaf(P##T1,F6,a1);  a1 = fmaf(P##T5,F10,a1);  a1 = fmaf(P##T9,F14,a1);  a1 = fmaf(P##T13,F18,a1); \
    float a2 = P##L12 * F3;        a2 = fmaf(P##T2,F7,a2);  a2 = fmaf(P##T6,F11,a2);  a2 = fmaf(P##T10,F15,a2); a2 = fmaf(P##T14,F19,a2); \
    float a3 = P##L13 * F4;        a3 = fmaf(P##T3,F8,a3);  a3 = fmaf(P##T7,F12,a3);  a3 = fmaf(P##T11,F16,a3); a3 = fmaf(P##T15,F20,a3); \
    float acc_ = (a0 + a1) + (a2 + a3); \
    P##fgn = sigm(fmaf(acc_, frcpa(P##tf), bf));  /* F prescaled by 4095; norm = 4095/t */ \
    P##ni = fmaf(xn2, Wi2, fmaf(xn1, Wi1, fmaf(xn0, Wi0, bi))); \
    P##nc = fmaf(xn2, Wc2, fmaf(xn1, Wc1, fmaf(xn0, Wc0, bc))); \
    P##no = fmaf(xn2, Wo2, fmaf(xn1, Wo1, fmaf(xn0, Wo0, bo))); \
} while (0)

// Full step T_ for one chain. Two chains' STEPs placed back-to-back in the loop body
// interleave in ptxas scheduling -> each fills the other's stall slots.
#define STEP(P, T_, S) do { \
    float h0 = __shfl_sync(0xFFu, P##h, 0); \
    float h1 = __shfl_sync(0xFFu, P##h, 1); \
    float h2 = __shfl_sync(0xFFu, P##h, 2); \
    float h3 = __shfl_sync(0xFFu, P##h, 3); \
    float h4 = __shfl_sync(0xFFu, P##h, 4); \
    float h5 = __shfl_sync(0xFFu, P##h, 5); \
    float h6 = __shfl_sync(0xFFu, P##h, 6); \
    float h7 = __shfl_sync(0xFFu, P##h, 7); \
    STEP_C(P, T_, S); \
    float giA = fmaf(h3,Ri3, fmaf(h2,Ri2, fmaf(h1,Ri1, fmaf(h0,Ri0, P##gi)))); \
    float giB = fmaf(h7,Ri7, fmaf(h6,Ri6, fmaf(h5,Ri5, h4 * Ri4))); \
    float gcA = fmaf(h3,Rc3, fmaf(h2,Rc2, fmaf(h1,Rc1, fmaf(h0,Rc0, P##gc)))); \
    float gcB = fmaf(h7,Rc7, fmaf(h6,Rc6, fmaf(h5,Rc5, h4 * Rc4))); \
    float goA = fmaf(h3,Ro3, fmaf(h2,Ro2, fmaf(h1,Ro1, fmaf(h0,Ro0, P##go)))); \
    float goB = fmaf(h7,Ro7, fmaf(h6,Ro6, fmaf(h5,Ro5, h4 * Ro4))); \
    float vi = sigm(giA + giB); \
    float vc = tanha(gcA + gcB); \
    float vo = sigm(goA + goB); \
    P##c = fmaf(P##fgv, P##c, vi * vc); \
    P##h = vo * tanha(P##c); \
    P##op[0] = P##h; P##op += 8; \
    P##fgv = P##fgn; P##gi = P##ni; P##gc = P##nc; P##go = P##no; \
} while (0)

// t = 0 (h0 = c0 = 0: gates from x-proj only, forget gate irrelevant) + ring fill + pipeline prime
#define PROLOGUE(P) do { \
    P##p0 = __ldg(P##xp); P##p1 = __ldg(P##xp + 1); P##p2 = __ldg(P##xp + 2); \
    float g0i = fmaf(P##p2, Wi2, fmaf(P##p1, Wi1, fmaf(P##p0, Wi0, bi))); \
    float g0c = fmaf(P##p2, Wc2, fmaf(P##p1, Wc1, fmaf(P##p0, Wc0, bc))); \
    float g0o = fmaf(P##p2, Wo2, fmaf(P##p1, Wo1, fmaf(P##p0, Wo0, bo))); \
    P##c = sigm(g0i) * tanha(g0c); \
    P##h = sigm(g0o) * tanha(P##c); \
    P##op[0] = P##h; P##op += 8; \
    P##x0_1 = __ldg(P##xp + 3);  P##x1_1 = __ldg(P##xp + 4);  P##x2_1 = __ldg(P##xp + 5); \
    P##x0_2 = __ldg(P##xp + 6);  P##x1_2 = __ldg(P##xp + 7);  P##x2_2 = __ldg(P##xp + 8); \
    P##x0_3 = __ldg(P##xp + 9);  P##x1_3 = __ldg(P##xp + 10); P##x2_3 = __ldg(P##xp + 11); \
    P##x0_0 = __ldg(P##xp + 12); P##x1_0 = __ldg(P##xp + 13); P##x2_0 = __ldg(P##xp + 14); \
    STEP_C(P, 0, 1); \
    P##fgv = P##fgn; P##gi = P##ni; P##gc = P##nc; P##go = P##no; \
} while (0)

__global__ void __launch_bounds__(32, 1) siglstm_kernel(
    const float* __restrict__ inp,   // (256, 4096, 3)
    const float* __restrict__ ik,    // (3, 24)
    const float* __restrict__ rk,    // (8, 24)
    const float* __restrict__ fk,    // (21, 8)
    const float* __restrict__ bias,  // (32)
    float* __restrict__ out)         // (256, 4096, 8)
{
    const int u = threadIdx.x;
    if (u >= 8) return;              // 8 active lanes; two batches per warp via ILP
    const int b0 = blockIdx.x * 2;

    // Shared weights (identical for both chains)
    const float Ri0=rk[0*24+u], Ri1=rk[1*24+u], Ri2=rk[2*24+u], Ri3=rk[3*24+u];
    const float Ri4=rk[4*24+u], Ri5=rk[5*24+u], Ri6=rk[6*24+u], Ri7=rk[7*24+u];
    const float Rc0=rk[0*24+8+u], Rc1=rk[1*24+8+u], Rc2=rk[2*24+8+u], Rc3=rk[3*24+8+u];
    const float Rc4=rk[4*24+8+u], Rc5=rk[5*24+8+u], Rc6=rk[6*24+8+u], Rc7=rk[7*24+8+u];
    const float Ro0=rk[0*24+16+u], Ro1=rk[1*24+16+u], Ro2=rk[2*24+16+u], Ro3=rk[3*24+16+u];
    const float Ro4=rk[4*24+16+u], Ro5=rk[5*24+16+u], Ro6=rk[6*24+16+u], Ro7=rk[7*24+16+u];
    const float Wi0=ik[0*24+u],    Wi1=ik[1*24+u],    Wi2=ik[2*24+u];
    const float Wc0=ik[0*24+8+u],  Wc1=ik[1*24+8+u],  Wc2=ik[2*24+8+u];
    const float Wo0=ik[0*24+16+u], Wo1=ik[1*24+16+u], Wo2=ik[2*24+16+u];
    const float bi=bias[u], bf=bias[8+u], bc=bias[16+u], bo=bias[24+u];

    const float SC = 4095.0f;        // fold sig-normalization numerator into F
    const float F0 =SC*fk[0*8+u],  F1 =SC*fk[1*8+u],  F2 =SC*fk[2*8+u],  F3 =SC*fk[3*8+u];
    const float F4 =SC*fk[4*8+u],  F5 =SC*fk[5*8+u],  F6 =SC*fk[6*8+u],  F7 =SC*fk[7*8+u];
    const float F8 =SC*fk[8*8+u],  F9 =SC*fk[9*8+u],  F10=SC*fk[10*8+u], F11=SC*fk[11*8+u];
    const float F12=SC*fk[12*8+u], F13=SC*fk[13*8+u], F14=SC*fk[14*8+u], F15=SC*fk[15*8+u];
    const float F16=SC*fk[16*8+u], F17=SC*fk[17*8+u], F18=SC*fk[18*8+u], F19=SC*fk[19*8+u];
    const float F20=SC*fk[20*8+u];

    const float DX0  = 1.0f / 4095.0f;   // time increment of the augmented path
    const float HDX0 = 0.5f * DX0;

    DECL_STATE(A)
    DECL_STATE(B)
    Axp = inp + (long)b0 * NT * 3;
    Bxp = inp + (long)(b0 + 1) * NT * 3;
    Aop = out + (long)b0 * NT * 8 + u;
    Bop = out + (long)(b0 + 1) * NT * 8 + u;

    PROLOGUE(A);
    PROLOGUE(B);

    // main loop: t = 1 .. 4092, unroll 4 (ring slot (t+1)&3 cycles 2,3,0,1)
    for (int blk = 0; blk < 1023; blk++) {
        const int t = blk * 4 + 1;
        STEP(A, t,     2);  STEP(B, t,     2);
        STEP(A, t + 1, 3);  STEP(B, t + 1, 3);
        STEP(A, t + 2, 0);  STEP(B, t + 2, 0);
        STEP(A, t + 3, 1);  STEP(B, t + 3, 1);
    }
    // tail: t = 4093, 4094, 4095
    STEP(A, 4093, 2);  STEP(B, 4093, 2);
    STEP(A, 4094, 3);  STEP(B, 4094, 3);
    STEP(A, 4095, 0);  STEP(B, 4095, 0);
}

extern "C" void kernel_launch(void* const* d_in, const int* in_sizes, int n_in,
                              void* d_out, int out_size)
{
    const float* inp  = (const float*)d_in[0];   // inputs (256,4096,3)
    const float* ik   = (const float*)d_in[1];   // input_kernel (3,24)
    const float* rk   = (const float*)d_in[2];   // recurrent_kernel (8,24)
    const float* fk   = (const float*)d_in[3];   // forget_kernel (21,8)
    const float* bias = (const float*)d_in[4];   // bias (32)
    float* out = (float*)d_out;                  // (256,4096,8) f32

    siglstm_kernel<<<128, 32>>>(inp, ik, rk, fk, bias, out);
}